// round 11
// baseline (speedup 1.0000x reference)
#include <cuda_runtime.h>
#include <cstdint>
#include <math_constants.h>

#define T_DIM 64
#define B_DIM 32
#define S_DIM 128
#define E_DIM 512
#define Q_DIM 512
#define H_DIM 256

#define GEMM_BK   32
#define GEMM_PAD  36   // floats per smem row (32 data + 4 pad): conflict-free frags

// Scratch (device globals — no allocation allowed)
__device__ float g_src_proj[B_DIM * H_DIM * S_DIM];   // [b][h][s]
__device__ float g_q_proj[T_DIM * B_DIM * H_DIM];     // [t][b][h]

__device__ __forceinline__ float ex2f_(float x) {
    float y; asm("ex2.approx.f32 %0, %1;" : "=f"(y) : "f"(x)); return y;
}
__device__ __forceinline__ float rcpf_(float x) {
    float y; asm("rcp.approx.f32 %0, %1;" : "=f"(y) : "f"(x)); return y;
}
__device__ __forceinline__ void mma_tf32(float c[4], const unsigned a[4], const unsigned b[2]) {
    asm volatile(
        "mma.sync.aligned.m16n8k8.row.col.f32.tf32.tf32.f32 "
        "{%0,%1,%2,%3}, {%4,%5,%6,%7}, {%8,%9}, {%0,%1,%2,%3};"
        : "+f"(c[0]), "+f"(c[1]), "+f"(c[2]), "+f"(c[3])
        : "r"(a[0]), "r"(a[1]), "r"(a[2]), "r"(a[3]), "r"(b[0]), "r"(b[1]));
}
__device__ __forceinline__ void cp_async16(uint32_t saddr, const void* gptr) {
    asm volatile("cp.async.cg.shared.global [%0], [%1], 16;" :: "r"(saddr), "l"(gptr));
}

// ---------------------------------------------------------------------------
// Tensor-core projection GEMM — TF32, cp.async double-buffered (unchanged).
// ---------------------------------------------------------------------------
__global__ __launch_bounds__(512) void proj_gemm(
    const float* __restrict__ src, const float* __restrict__ Wsrc, const float* __restrict__ bsrc,
    const float* __restrict__ qv,  const float* __restrict__ Wq,   const float* __restrict__ bq)
{
    extern __shared__ float sm[];
    float* As = sm;                        // [2][128][GEMM_PAD]
    float* Bs = sm + 2 * 128 * GEMM_PAD;   // [2][64][GEMM_PAD]

    const int bx = blockIdx.x;      // 0..47
    const int n0 = blockIdx.y * 64; // h tile base

    const bool is_src = (bx < 32);
    const float* __restrict__ A    = is_src ? (src + (size_t)bx * 128 * E_DIM)
                                            : (qv  + (size_t)(bx - 32) * 128 * Q_DIM);
    const float* __restrict__ W    = is_src ? Wsrc : Wq;
    const float* __restrict__ bias = is_src ? bsrc : bq;

    const int tid  = threadIdx.x;
    const int warp = tid >> 5;
    const int lane = tid & 31;
    const int wm   = (warp & 3) * 32;
    const int wn   = (warp >> 2) * 16;
    const int frow = lane >> 2;
    const int fcol = lane & 3;

    const uint32_t As_base = (uint32_t)__cvta_generic_to_shared(As);
    const uint32_t Bs_base = (uint32_t)__cvta_generic_to_shared(Bs);

    float acc[2][2][4];
#pragma unroll
    for (int i = 0; i < 2; i++)
#pragma unroll
        for (int j = 0; j < 2; j++)
#pragma unroll
            for (int r = 0; r < 4; r++) acc[i][j][r] = 0.f;

    auto load_chunk = [&](int kc, int buf) {
        const int kt = kc * GEMM_BK;
        const uint32_t abuf = As_base + (uint32_t)buf * 128 * GEMM_PAD * 4;
        const uint32_t bbuf = Bs_base + (uint32_t)buf * 64 * GEMM_PAD * 4;
#pragma unroll
        for (int j = 0; j < 2; j++) {
            const int v = tid + j * 512;
            const int r = v >> 3;
            const int c = (v & 7) * 4;
            cp_async16(abuf + (uint32_t)(r * GEMM_PAD + c) * 4,
                       &A[(size_t)r * 512 + kt + c]);
        }
        {
            const int r = tid >> 3;
            const int c = (tid & 7) * 4;
            cp_async16(bbuf + (uint32_t)(r * GEMM_PAD + c) * 4,
                       &W[(size_t)(n0 + r) * 512 + kt + c]);
        }
        asm volatile("cp.async.commit_group;");
    };

    load_chunk(0, 0);

    for (int kc = 0; kc < 16; kc++) {
        if (kc + 1 < 16) {
            load_chunk(kc + 1, (kc + 1) & 1);
            asm volatile("cp.async.wait_group 1;");
        } else {
            asm volatile("cp.async.wait_group 0;");
        }
        __syncthreads();

        const int buf = kc & 1;
        const float* Ab = As + buf * 128 * GEMM_PAD;
        const float* Bb = Bs + buf * 64 * GEMM_PAD;

#pragma unroll
        for (int ks = 0; ks < 4; ks++) {
            const int k0 = ks * 8;
            unsigned ah[2][4];
#pragma unroll
            for (int mf = 0; mf < 2; mf++) {
                const int m = wm + mf * 16;
                ah[mf][0] = __float_as_uint(Ab[(m + frow    ) * GEMM_PAD + k0 + fcol    ]);
                ah[mf][1] = __float_as_uint(Ab[(m + frow + 8) * GEMM_PAD + k0 + fcol    ]);
                ah[mf][2] = __float_as_uint(Ab[(m + frow    ) * GEMM_PAD + k0 + fcol + 4]);
                ah[mf][3] = __float_as_uint(Ab[(m + frow + 8) * GEMM_PAD + k0 + fcol + 4]);
            }
            unsigned bh[2][2];
#pragma unroll
            for (int nf = 0; nf < 2; nf++) {
                const int n = wn + nf * 8;
                bh[nf][0] = __float_as_uint(Bb[(n + frow) * GEMM_PAD + k0 + fcol    ]);
                bh[nf][1] = __float_as_uint(Bb[(n + frow) * GEMM_PAD + k0 + fcol + 4]);
            }
#pragma unroll
            for (int mf = 0; mf < 2; mf++)
#pragma unroll
                for (int nf = 0; nf < 2; nf++)
                    mma_tf32(acc[mf][nf], ah[mf], bh[nf]);
        }
        __syncthreads();
    }

    const int crow = lane >> 2;
    const int ccol = (lane & 3) * 2;

    if (is_src) {
        const int b = bx;
        float* dst = g_src_proj + (size_t)b * H_DIM * S_DIM;
#pragma unroll
        for (int mf = 0; mf < 2; mf++)
#pragma unroll
            for (int nf = 0; nf < 2; nf++) {
                const int s0  = wm + mf * 16 + crow;
                const int h0g = n0 + wn + nf * 8 + ccol;
                dst[(h0g    ) * S_DIM + s0    ] = acc[mf][nf][0] + bias[h0g    ];
                dst[(h0g + 1) * S_DIM + s0    ] = acc[mf][nf][1] + bias[h0g + 1];
                dst[(h0g    ) * S_DIM + s0 + 8] = acc[mf][nf][2] + bias[h0g    ];
                dst[(h0g + 1) * S_DIM + s0 + 8] = acc[mf][nf][3] + bias[h0g + 1];
            }
    } else {
        const int m0 = (bx - 32) * 128;
#pragma unroll
        for (int mf = 0; mf < 2; mf++)
#pragma unroll
            for (int nf = 0; nf < 2; nf++) {
                const int m   = m0 + wm + mf * 16 + crow;
                const int h0g = n0 + wn + nf * 8 + ccol;
                g_q_proj[(size_t)m * H_DIM + h0g    ]       = acc[mf][nf][0] + bias[h0g    ];
                g_q_proj[(size_t)m * H_DIM + h0g + 1]       = acc[mf][nf][1] + bias[h0g + 1];
                g_q_proj[(size_t)(m + 8) * H_DIM + h0g    ] = acc[mf][nf][2] + bias[h0g    ];
                g_q_proj[(size_t)(m + 8) * H_DIM + h0g + 1] = acc[mf][nf][3] + bias[h0g + 1];
            }
    }
}

// ---------------------------------------------------------------------------
// Fused kernel (TT=4, 512 CTAs), ALL-t factored exponent + MUFU.RCP:
//   tanh(sv+q) = 1 - 2/(1 + E*Eq),  E = ex2(2*log2e*sv) shared per h-iter,
//   Eq[t][h] = ex2(2*log2e*q) precomputed in smem as float4 per h.
// Per h-iter: 1 LDG + 1 LDS.128 + 1 LDS.32 + 1 mul + 1 ex2 + 4x(fma,rcp,fma).
// part[tt][hg][s] stores (sum_w_quarter - 2*sum(w*r)).
// ---------------------------------------------------------------------------
__global__ __launch_bounds__(512) void fused_attn(
    const float* __restrict__ w2, const float* __restrict__ b2p,
    const int* __restrict__ mask, float* __restrict__ out)
{
    const int b   = blockIdx.y;
    const int tg  = blockIdx.x;
    const int tid = threadIdx.x;
    const int s   = tid & 127;
    const int hg  = tid >> 7;

    __shared__ float4 qsv[H_DIM];         // qsv[h] = {Eq_t0, Eq_t1, Eq_t2, Eq_t3}
    __shared__ float  w2s[H_DIM];
    __shared__ float  part[4][4][S_DIM];
    __shared__ float  redm[4][4];
    __shared__ float  reds[4][4];

    const float LOG2E     = 1.442695040888963407f;
    const float TWO_LOG2E = 2.885390081777926815f;

    for (int idx = tid; idx < 4 * H_DIM; idx += 512) {
        const int tt = idx >> 8;
        const int h  = idx & (H_DIM - 1);
        const int t  = tg * 4 + tt;
        const float q = g_q_proj[((size_t)t * B_DIM + b) * H_DIM + h];
        ((float*)qsv)[h * 4 + tt] = ex2f_(q * TWO_LOG2E);
    }
    if (tid < H_DIM) w2s[tid] = w2[tid];
    __syncthreads();

    const float* __restrict__ srcb = g_src_proj + (size_t)b * H_DIM * S_DIM + s;
    const int h0 = hg * 64;

    float a0 = 0.f, a1 = 0.f, a2 = 0.f, a3 = 0.f, wsum = 0.f;
#pragma unroll 4
    for (int i = 0; i < 64; i++) {
        const int h = h0 + i;
        const float sv = srcb[h * S_DIM];
        const float w  = w2s[h];
        wsum += w;
        const float E = ex2f_(sv * TWO_LOG2E);   // e^{2*sv}
        const float4 eq = qsv[h];
        a0 = fmaf(w, rcpf_(fmaf(E, eq.x, 1.f)), a0);
        a1 = fmaf(w, rcpf_(fmaf(E, eq.y, 1.f)), a1);
        a2 = fmaf(w, rcpf_(fmaf(E, eq.z, 1.f)), a2);
        a3 = fmaf(w, rcpf_(fmaf(E, eq.w, 1.f)), a3);
    }
    part[0][hg][s] = fmaf(-2.f, a0, wsum);   // sum w*tanh over this H-quarter
    part[1][hg][s] = fmaf(-2.f, a1, wsum);
    part[2][hg][s] = fmaf(-2.f, a2, wsum);
    part[3][hg][s] = fmaf(-2.f, a3, wsum);
    __syncthreads();

    float logit = ((part[hg][0][s] + part[hg][1][s]) +
                   (part[hg][2][s] + part[hg][3][s])) + b2p[0];
    if (mask[b * S_DIM + s] != 0)
        logit = __int_as_float(0xff800000);

    const int lane = tid & 31;
    const int gw   = (tid >> 5) & 3;

    float m = logit;
#pragma unroll
    for (int off = 16; off >= 1; off >>= 1)
        m = fmaxf(m, __shfl_xor_sync(0xffffffffu, m, off));
    if (lane == 0) redm[hg][gw] = m;
    __syncthreads();

    const float bm = fmaxf(fmaxf(redm[hg][0], redm[hg][1]),
                           fmaxf(redm[hg][2], redm[hg][3]));
    const float e = ex2f_((logit - bm) * LOG2E);
    float sum = e;
#pragma unroll
    for (int off = 16; off >= 1; off >>= 1)
        sum += __shfl_xor_sync(0xffffffffu, sum, off);
    if (lane == 0) reds[hg][gw] = sum;
    __syncthreads();

    const float tot = (reds[hg][0] + reds[hg][1]) + (reds[hg][2] + reds[hg][3]);
    const int t = tg * 4 + hg;
    out[((size_t)t * B_DIM + b) * S_DIM + s] = e / tot;
}

extern "C" void kernel_launch(void* const* d_in, const int* in_sizes, int n_in,
                              void* d_out, int out_size)
{
    const float* src  = (const float*)d_in[0];
    const int*   mask = (const int*)d_in[1];
    const float* qv   = (const float*)d_in[2];
    const float* Wsrc = (const float*)d_in[3];
    const float* bsrc = (const float*)d_in[4];
    const float* Wq   = (const float*)d_in[5];
    const float* bq   = (const float*)d_in[6];
    const float* w2   = (const float*)d_in[7];
    const float* b2   = (const float*)d_in[8];
    float*       out  = (float*)d_out;

    const int gemm_smem = (2 * 128 * GEMM_PAD + 2 * 64 * GEMM_PAD) * 4;  // 55296
    cudaFuncSetAttribute(proj_gemm, cudaFuncAttributeMaxDynamicSharedMemorySize, gemm_smem);

    dim3 g1(48, 4);
    proj_gemm<<<g1, 512, gemm_smem>>>(src, Wsrc, bsrc, qv, Wq, bq);

    dim3 g2(T_DIM / 4, B_DIM);
    fused_attn<<<g2, 512>>>(w2, b2, mask, out);
}

// round 12
// speedup vs baseline: 1.1915x; 1.1915x over previous
#include <cuda_runtime.h>
#include <cstdint>
#include <math_constants.h>

#define T_DIM 64
#define B_DIM 32
#define S_DIM 128
#define E_DIM 512
#define Q_DIM 512
#define H_DIM 256

#define GEMM_BK   32
#define GEMM_PAD  36   // floats per smem row (32 data + 4 pad): conflict-free frags

#define FUSED_TT  8    // t's per fused CTA: 4 TANH-path + 4 Newton-path

// Scratch (device globals — no allocation allowed)
__device__ float g_src_proj[B_DIM * H_DIM * S_DIM];   // [b][h][s]
__device__ float g_q_proj[T_DIM * B_DIM * H_DIM];     // [t][b][h]

__device__ __forceinline__ float ex2f_(float x) {
    float y; asm("ex2.approx.f32 %0, %1;" : "=f"(y) : "f"(x)); return y;
}
__device__ __forceinline__ float tanhf_(float x) {
    float y; asm("tanh.approx.f32 %0, %1;" : "=f"(y) : "f"(x)); return y;
}
__device__ __forceinline__ void mma_tf32(float c[4], const unsigned a[4], const unsigned b[2]) {
    asm volatile(
        "mma.sync.aligned.m16n8k8.row.col.f32.tf32.tf32.f32 "
        "{%0,%1,%2,%3}, {%4,%5,%6,%7}, {%8,%9}, {%0,%1,%2,%3};"
        : "+f"(c[0]), "+f"(c[1]), "+f"(c[2]), "+f"(c[3])
        : "r"(a[0]), "r"(a[1]), "r"(a[2]), "r"(a[3]), "r"(b[0]), "r"(b[1]));
}
__device__ __forceinline__ void cp_async16(uint32_t saddr, const void* gptr) {
    asm volatile("cp.async.cg.shared.global [%0], [%1], 16;" :: "r"(saddr), "l"(gptr));
}

// ---------------------------------------------------------------------------
// Tensor-core projection GEMM — TF32, cp.async double-buffered (unchanged).
// ---------------------------------------------------------------------------
__global__ __launch_bounds__(512) void proj_gemm(
    const float* __restrict__ src, const float* __restrict__ Wsrc, const float* __restrict__ bsrc,
    const float* __restrict__ qv,  const float* __restrict__ Wq,   const float* __restrict__ bq)
{
    extern __shared__ float sm[];
    float* As = sm;                        // [2][128][GEMM_PAD]
    float* Bs = sm + 2 * 128 * GEMM_PAD;   // [2][64][GEMM_PAD]

    const int bx = blockIdx.x;      // 0..47
    const int n0 = blockIdx.y * 64; // h tile base

    const bool is_src = (bx < 32);
    const float* __restrict__ A    = is_src ? (src + (size_t)bx * 128 * E_DIM)
                                            : (qv  + (size_t)(bx - 32) * 128 * Q_DIM);
    const float* __restrict__ W    = is_src ? Wsrc : Wq;
    const float* __restrict__ bias = is_src ? bsrc : bq;

    const int tid  = threadIdx.x;
    const int warp = tid >> 5;
    const int lane = tid & 31;
    const int wm   = (warp & 3) * 32;
    const int wn   = (warp >> 2) * 16;
    const int frow = lane >> 2;
    const int fcol = lane & 3;

    const uint32_t As_base = (uint32_t)__cvta_generic_to_shared(As);
    const uint32_t Bs_base = (uint32_t)__cvta_generic_to_shared(Bs);

    float acc[2][2][4];
#pragma unroll
    for (int i = 0; i < 2; i++)
#pragma unroll
        for (int j = 0; j < 2; j++)
#pragma unroll
            for (int r = 0; r < 4; r++) acc[i][j][r] = 0.f;

    auto load_chunk = [&](int kc, int buf) {
        const int kt = kc * GEMM_BK;
        const uint32_t abuf = As_base + (uint32_t)buf * 128 * GEMM_PAD * 4;
        const uint32_t bbuf = Bs_base + (uint32_t)buf * 64 * GEMM_PAD * 4;
#pragma unroll
        for (int j = 0; j < 2; j++) {
            const int v = tid + j * 512;
            const int r = v >> 3;
            const int c = (v & 7) * 4;
            cp_async16(abuf + (uint32_t)(r * GEMM_PAD + c) * 4,
                       &A[(size_t)r * 512 + kt + c]);
        }
        {
            const int r = tid >> 3;
            const int c = (tid & 7) * 4;
            cp_async16(bbuf + (uint32_t)(r * GEMM_PAD + c) * 4,
                       &W[(size_t)(n0 + r) * 512 + kt + c]);
        }
        asm volatile("cp.async.commit_group;");
    };

    load_chunk(0, 0);

    for (int kc = 0; kc < 16; kc++) {
        if (kc + 1 < 16) {
            load_chunk(kc + 1, (kc + 1) & 1);
            asm volatile("cp.async.wait_group 1;");
        } else {
            asm volatile("cp.async.wait_group 0;");
        }
        __syncthreads();

        const int buf = kc & 1;
        const float* Ab = As + buf * 128 * GEMM_PAD;
        const float* Bb = Bs + buf * 64 * GEMM_PAD;

#pragma unroll
        for (int ks = 0; ks < 4; ks++) {
            const int k0 = ks * 8;
            unsigned ah[2][4];
#pragma unroll
            for (int mf = 0; mf < 2; mf++) {
                const int m = wm + mf * 16;
                ah[mf][0] = __float_as_uint(Ab[(m + frow    ) * GEMM_PAD + k0 + fcol    ]);
                ah[mf][1] = __float_as_uint(Ab[(m + frow + 8) * GEMM_PAD + k0 + fcol    ]);
                ah[mf][2] = __float_as_uint(Ab[(m + frow    ) * GEMM_PAD + k0 + fcol + 4]);
                ah[mf][3] = __float_as_uint(Ab[(m + frow + 8) * GEMM_PAD + k0 + fcol + 4]);
            }
            unsigned bh[2][2];
#pragma unroll
            for (int nf = 0; nf < 2; nf++) {
                const int n = wn + nf * 8;
                bh[nf][0] = __float_as_uint(Bb[(n + frow) * GEMM_PAD + k0 + fcol    ]);
                bh[nf][1] = __float_as_uint(Bb[(n + frow) * GEMM_PAD + k0 + fcol + 4]);
            }
#pragma unroll
            for (int mf = 0; mf < 2; mf++)
#pragma unroll
                for (int nf = 0; nf < 2; nf++)
                    mma_tf32(acc[mf][nf], ah[mf], bh[nf]);
        }
        __syncthreads();
    }

    const int crow = lane >> 2;
    const int ccol = (lane & 3) * 2;

    if (is_src) {
        const int b = bx;
        float* dst = g_src_proj + (size_t)b * H_DIM * S_DIM;
#pragma unroll
        for (int mf = 0; mf < 2; mf++)
#pragma unroll
            for (int nf = 0; nf < 2; nf++) {
                const int s0  = wm + mf * 16 + crow;
                const int h0g = n0 + wn + nf * 8 + ccol;
                dst[(h0g    ) * S_DIM + s0    ] = acc[mf][nf][0] + bias[h0g    ];
                dst[(h0g + 1) * S_DIM + s0    ] = acc[mf][nf][1] + bias[h0g + 1];
                dst[(h0g    ) * S_DIM + s0 + 8] = acc[mf][nf][2] + bias[h0g    ];
                dst[(h0g + 1) * S_DIM + s0 + 8] = acc[mf][nf][3] + bias[h0g + 1];
            }
    } else {
        const int m0 = (bx - 32) * 128;
#pragma unroll
        for (int mf = 0; mf < 2; mf++)
#pragma unroll
            for (int nf = 0; nf < 2; nf++) {
                const int m   = m0 + wm + mf * 16 + crow;
                const int h0g = n0 + wn + nf * 8 + ccol;
                g_q_proj[(size_t)m * H_DIM + h0g    ]       = acc[mf][nf][0] + bias[h0g    ];
                g_q_proj[(size_t)m * H_DIM + h0g + 1]       = acc[mf][nf][1] + bias[h0g + 1];
                g_q_proj[(size_t)(m + 8) * H_DIM + h0g    ] = acc[mf][nf][2] + bias[h0g    ];
                g_q_proj[(size_t)(m + 8) * H_DIM + h0g + 1] = acc[mf][nf][3] + bias[h0g + 1];
            }
    }
}

// ---------------------------------------------------------------------------
// Fused kernel, TT=8 (grid 256 = single wave at 2 CTA/SM), dual-pipe tanh:
//   tt 0..3: MUFU.TANH (16 cyc each, MUFU pipe)
//   tt 4..7: tanh = 1 - 2/(1 + E*Eq): ONE shared E = ex2(2*log2e*sv) per iter,
//            Eq precomputed in smem; rcp via bit-seed + 2 Newton (FMA pipe).
// Per warp-iter: MUFU 80 cyc vs FMA ~70 cyc -> balanced.
// part rows 4..7 store (wsum_quarter - 2*acc); rows 0..3 store acc directly.
// ---------------------------------------------------------------------------
__global__ __launch_bounds__(512) void fused_attn(
    const float* __restrict__ w2, const float* __restrict__ b2p,
    const int* __restrict__ mask, float* __restrict__ out)
{
    const int b   = blockIdx.y;
    const int tg  = blockIdx.x;            // t = tg*8 + tt
    const int tid = threadIdx.x;
    const int s   = tid & 127;
    const int hg  = tid >> 7;              // 0..3, H-quarter

    __shared__ float4 qtv[H_DIM];          // raw q for tt 0..3
    __shared__ float4 qev[H_DIM];          // Eq = 2^(2q*log2e) for tt 4..7
    __shared__ float  w2s[H_DIM];
    __shared__ float  part[FUSED_TT][4][S_DIM];
    __shared__ float  redm[FUSED_TT][4];
    __shared__ float  reds[FUSED_TT][4];

    const float LOG2E     = 1.442695040888963407f;
    const float TWO_LOG2E = 2.885390081777926815f;

    for (int idx = tid; idx < FUSED_TT * H_DIM; idx += 512) {
        const int tt = idx >> 8;           // 0..7
        const int h  = idx & (H_DIM - 1);
        const int t  = tg * FUSED_TT + tt;
        const float q = g_q_proj[((size_t)t * B_DIM + b) * H_DIM + h];
        if (tt < 4) ((float*)qtv)[h * 4 + tt] = q;
        else        ((float*)qev)[h * 4 + (tt - 4)] = ex2f_(q * TWO_LOG2E);
    }
    if (tid < H_DIM) w2s[tid] = w2[tid];
    __syncthreads();

    const float* __restrict__ srcb = g_src_proj + (size_t)b * H_DIM * S_DIM + s;
    const int h0 = hg * 64;

    float acc[FUSED_TT];
#pragma unroll
    for (int tt = 0; tt < FUSED_TT; tt++) acc[tt] = 0.f;
    float wsum = 0.f;

#pragma unroll 4
    for (int i = 0; i < 64; i++) {
        const int h = h0 + i;
        const float sv = srcb[h * S_DIM];
        const float w  = w2s[h];
        wsum += w;
        // --- TANH path (tt 0..3) ---
        const float4 qt = qtv[h];
        acc[0] = fmaf(w, tanhf_(sv + qt.x), acc[0]);
        acc[1] = fmaf(w, tanhf_(sv + qt.y), acc[1]);
        acc[2] = fmaf(w, tanhf_(sv + qt.z), acc[2]);
        acc[3] = fmaf(w, tanhf_(sv + qt.w), acc[3]);
        // --- shared-E Newton path (tt 4..7) ---
        const float E = ex2f_(sv * TWO_LOG2E);
        const float4 eq = qev[h];
        {
            const float d = fmaf(E, eq.x, 1.f);
            float r = __uint_as_float(0x7EF311C3u - __float_as_uint(d));
            r = r * fmaf(-d, r, 2.f);
            r = r * fmaf(-d, r, 2.f);
            acc[4] = fmaf(w, r, acc[4]);
        }
        {
            const float d = fmaf(E, eq.y, 1.f);
            float r = __uint_as_float(0x7EF311C3u - __float_as_uint(d));
            r = r * fmaf(-d, r, 2.f);
            r = r * fmaf(-d, r, 2.f);
            acc[5] = fmaf(w, r, acc[5]);
        }
        {
            const float d = fmaf(E, eq.z, 1.f);
            float r = __uint_as_float(0x7EF311C3u - __float_as_uint(d));
            r = r * fmaf(-d, r, 2.f);
            r = r * fmaf(-d, r, 2.f);
            acc[6] = fmaf(w, r, acc[6]);
        }
        {
            const float d = fmaf(E, eq.w, 1.f);
            float r = __uint_as_float(0x7EF311C3u - __float_as_uint(d));
            r = r * fmaf(-d, r, 2.f);
            r = r * fmaf(-d, r, 2.f);
            acc[7] = fmaf(w, r, acc[7]);
        }
    }

#pragma unroll
    for (int tt = 0; tt < 4; tt++)
        part[tt][hg][s] = acc[tt];
#pragma unroll
    for (int tt = 4; tt < 8; tt++)
        part[tt][hg][s] = fmaf(-2.f, acc[tt], wsum);
    __syncthreads();

    // Each hg group finishes softmax for tt = hg*2, hg*2+1.
    const int lane = tid & 31;
    const int gw   = (tid >> 5) & 3;
    const float b2v = b2p[0];
    const bool masked = (mask[b * S_DIM + s] != 0);

    float logit[2];
#pragma unroll
    for (int j = 0; j < 2; j++) {
        const int tt = hg * 2 + j;
        float lg = ((part[tt][0][s] + part[tt][1][s]) +
                    (part[tt][2][s] + part[tt][3][s])) + b2v;
        if (masked) lg = __int_as_float(0xff800000);
        logit[j] = lg;

        float m = lg;
#pragma unroll
        for (int off = 16; off >= 1; off >>= 1)
            m = fmaxf(m, __shfl_xor_sync(0xffffffffu, m, off));
        if (lane == 0) redm[tt][gw] = m;
    }
    __syncthreads();

    float e[2];
#pragma unroll
    for (int j = 0; j < 2; j++) {
        const int tt = hg * 2 + j;
        const float bm = fmaxf(fmaxf(redm[tt][0], redm[tt][1]),
                               fmaxf(redm[tt][2], redm[tt][3]));
        e[j] = ex2f_((logit[j] - bm) * LOG2E);
        float sum = e[j];
#pragma unroll
        for (int off = 16; off >= 1; off >>= 1)
            sum += __shfl_xor_sync(0xffffffffu, sum, off);
        if (lane == 0) reds[tt][gw] = sum;
    }
    __syncthreads();

#pragma unroll
    for (int j = 0; j < 2; j++) {
        const int tt = hg * 2 + j;
        const float tot = (reds[tt][0] + reds[tt][1]) + (reds[tt][2] + reds[tt][3]);
        const int t = tg * FUSED_TT + tt;
        out[((size_t)t * B_DIM + b) * S_DIM + s] = e[j] / tot;
    }
}

extern "C" void kernel_launch(void* const* d_in, const int* in_sizes, int n_in,
                              void* d_out, int out_size)
{
    const float* src  = (const float*)d_in[0];
    const int*   mask = (const int*)d_in[1];
    const float* qv   = (const float*)d_in[2];
    const float* Wsrc = (const float*)d_in[3];
    const float* bsrc = (const float*)d_in[4];
    const float* Wq   = (const float*)d_in[5];
    const float* bq   = (const float*)d_in[6];
    const float* w2   = (const float*)d_in[7];
    const float* b2   = (const float*)d_in[8];
    float*       out  = (float*)d_out;

    const int gemm_smem = (2 * 128 * GEMM_PAD + 2 * 64 * GEMM_PAD) * 4;  // 55296
    cudaFuncSetAttribute(proj_gemm, cudaFuncAttributeMaxDynamicSharedMemorySize, gemm_smem);

    dim3 g1(48, 4);
    proj_gemm<<<g1, 512, gemm_smem>>>(src, Wsrc, bsrc, qv, Wq, bq);

    dim3 g2(T_DIM / FUSED_TT, B_DIM);
    fused_attn<<<g2, 512>>>(w2, b2, mask, out);
}

// round 13
// speedup vs baseline: 1.3208x; 1.1085x over previous
#include <cuda_runtime.h>
#include <cuda_fp16.h>
#include <cstdint>
#include <math_constants.h>

#define T_DIM 64
#define B_DIM 32
#define S_DIM 128
#define E_DIM 512
#define Q_DIM 512
#define H_DIM 256

#define HSTR 40   // halves per smem row (32 data + 8 pad) = 80B = 20 banks -> conflict-free frags

// Scratch (device globals — no allocation allowed)
__device__ float g_src_proj[B_DIM * H_DIM * S_DIM];   // [b][h][s]
__device__ float g_q_proj[T_DIM * B_DIM * H_DIM];     // [t][b][h]

__device__ __forceinline__ float ex2f_(float x) {
    float y; asm("ex2.approx.f32 %0, %1;" : "=f"(y) : "f"(x)); return y;
}
__device__ __forceinline__ float tanhf_(float x) {
    float y; asm("tanh.approx.f32 %0, %1;" : "=f"(y) : "f"(x)); return y;
}
__device__ __forceinline__ void mma_f16(float c[4], const unsigned a[4], const unsigned b[2]) {
    asm volatile(
        "mma.sync.aligned.m16n8k16.row.col.f32.f16.f16.f32 "
        "{%0,%1,%2,%3}, {%4,%5,%6,%7}, {%8,%9}, {%0,%1,%2,%3};"
        : "+f"(c[0]), "+f"(c[1]), "+f"(c[2]), "+f"(c[3])
        : "r"(a[0]), "r"(a[1]), "r"(a[2]), "r"(a[3]), "r"(b[0]), "r"(b[1]));
}

// ---------------------------------------------------------------------------
// FP16 tensor-core projection GEMM (f32 in/out, fp16 MMA, RNE convert).
// C[m,h] = sum_k A[m,k] * W[h,k] + bias[h],  K=512, BK=32 (2 k16-steps).
// blockIdx.x in [0,32): src path, out transposed [b][h][s].
// blockIdx.x in [32,48): query path, out row-major [m][h].
// CTA tile 128(m) x 64(n), 512 thr = 16 warps (4m x 4n), warp 32x16.
// Reg-staged double buffer: LDG f32 -> cvt -> STS half2. One sync per chunk:
// STS targets buffer (kc+1)&1, which all warps finished READING in iter kc-1,
// guaranteed by the sync at the top of iter kc.
// ---------------------------------------------------------------------------
__global__ __launch_bounds__(512) void proj_gemm(
    const float* __restrict__ src, const float* __restrict__ Wsrc, const float* __restrict__ bsrc,
    const float* __restrict__ qv,  const float* __restrict__ Wq,   const float* __restrict__ bq)
{
    __shared__ __align__(16) __half As[2][128][HSTR];   // 20.5 KB
    __shared__ __align__(16) __half Bs[2][64][HSTR];    // 10.2 KB

    const int bx = blockIdx.x;      // 0..47
    const int n0 = blockIdx.y * 64; // h tile base

    const bool is_src = (bx < 32);
    const float* __restrict__ A    = is_src ? (src + (size_t)bx * 128 * E_DIM)
                                            : (qv  + (size_t)(bx - 32) * 128 * Q_DIM);
    const float* __restrict__ W    = is_src ? Wsrc : Wq;
    const float* __restrict__ bias = is_src ? bsrc : bq;

    const int tid  = threadIdx.x;
    const int warp = tid >> 5;
    const int lane = tid & 31;
    const int wm   = (warp & 3) * 32;
    const int wn   = (warp >> 2) * 16;
    const int frow = lane >> 2;         // 0..7
    const int fcol = lane & 3;          // 0..3

    float acc[2][2][4];
#pragma unroll
    for (int i = 0; i < 2; i++)
#pragma unroll
        for (int j = 0; j < 2; j++)
#pragma unroll
            for (int r = 0; r < 4; r++) acc[i][j][r] = 0.f;

    // reg staging: A 2 float4 / thread, B 1 float4 / thread
    float4 ra0, ra1, rb;
    const int a_r0 = tid >> 3;               // 0..63
    const int a_r1 = (tid + 512) >> 3;       // 64..127
    const int a_c  = (tid & 7) * 4;          // 0..28

    auto ldg_chunk = [&](int kc) {
        const int kt = kc * 32;
        ra0 = *(const float4*)&A[(size_t)a_r0 * 512 + kt + a_c];
        ra1 = *(const float4*)&A[(size_t)a_r1 * 512 + kt + a_c];
        rb  = *(const float4*)&W[(size_t)(n0 + a_r0) * 512 + kt + a_c];
    };
    auto sts_chunk = [&](int buf) {
        *(__half2*)&As[buf][a_r0][a_c    ] = __floats2half2_rn(ra0.x, ra0.y);
        *(__half2*)&As[buf][a_r0][a_c + 2] = __floats2half2_rn(ra0.z, ra0.w);
        *(__half2*)&As[buf][a_r1][a_c    ] = __floats2half2_rn(ra1.x, ra1.y);
        *(__half2*)&As[buf][a_r1][a_c + 2] = __floats2half2_rn(ra1.z, ra1.w);
        *(__half2*)&Bs[buf][a_r0][a_c    ] = __floats2half2_rn(rb.x, rb.y);
        *(__half2*)&Bs[buf][a_r0][a_c + 2] = __floats2half2_rn(rb.z, rb.w);
    };

    ldg_chunk(0);
    sts_chunk(0);

    for (int kc = 0; kc < 16; kc++) {
        __syncthreads();   // sts(kc) visible; all warps done reading buf (kc+1)&1 (iter kc-1)
        if (kc + 1 < 16) ldg_chunk(kc + 1);

        const int buf = kc & 1;
#pragma unroll
        for (int ks = 0; ks < 2; ks++) {
            const int k0 = ks * 16;
            const int kb = k0 + fcol * 2;
            unsigned ah[2][4];
#pragma unroll
            for (int mf = 0; mf < 2; mf++) {
                const int m = wm + mf * 16 + frow;
                ah[mf][0] = *(const unsigned*)&As[buf][m    ][kb    ];
                ah[mf][1] = *(const unsigned*)&As[buf][m + 8][kb    ];
                ah[mf][2] = *(const unsigned*)&As[buf][m    ][kb + 8];
                ah[mf][3] = *(const unsigned*)&As[buf][m + 8][kb + 8];
            }
            unsigned bh[2][2];
#pragma unroll
            for (int nf = 0; nf < 2; nf++) {
                const int n = wn + nf * 8 + frow;
                bh[nf][0] = *(const unsigned*)&Bs[buf][n][kb    ];
                bh[nf][1] = *(const unsigned*)&Bs[buf][n][kb + 8];
            }
#pragma unroll
            for (int mf = 0; mf < 2; mf++)
#pragma unroll
                for (int nf = 0; nf < 2; nf++)
                    mma_f16(acc[mf][nf], ah[mf], bh[nf]);
        }

        if (kc + 1 < 16) sts_chunk((kc + 1) & 1);
    }

    // --- epilogue (f32 c-frag layout identical to tf32 version) ---
    const int crow = lane >> 2;
    const int ccol = (lane & 3) * 2;

    if (is_src) {
        const int b = bx;
        float* dst = g_src_proj + (size_t)b * H_DIM * S_DIM;
#pragma unroll
        for (int mf = 0; mf < 2; mf++)
#pragma unroll
            for (int nf = 0; nf < 2; nf++) {
                const int s0  = wm + mf * 16 + crow;
                const int h0g = n0 + wn + nf * 8 + ccol;
                dst[(h0g    ) * S_DIM + s0    ] = acc[mf][nf][0] + bias[h0g    ];
                dst[(h0g + 1) * S_DIM + s0    ] = acc[mf][nf][1] + bias[h0g + 1];
                dst[(h0g    ) * S_DIM + s0 + 8] = acc[mf][nf][2] + bias[h0g    ];
                dst[(h0g + 1) * S_DIM + s0 + 8] = acc[mf][nf][3] + bias[h0g + 1];
            }
    } else {
        const int m0 = (bx - 32) * 128;
#pragma unroll
        for (int mf = 0; mf < 2; mf++)
#pragma unroll
            for (int nf = 0; nf < 2; nf++) {
                const int m   = m0 + wm + mf * 16 + crow;
                const int h0g = n0 + wn + nf * 8 + ccol;
                g_q_proj[(size_t)m * H_DIM + h0g    ]       = acc[mf][nf][0] + bias[h0g    ];
                g_q_proj[(size_t)m * H_DIM + h0g + 1]       = acc[mf][nf][1] + bias[h0g + 1];
                g_q_proj[(size_t)(m + 8) * H_DIM + h0g    ] = acc[mf][nf][2] + bias[h0g    ];
                g_q_proj[(size_t)(m + 8) * H_DIM + h0g + 1] = acc[mf][nf][3] + bias[h0g + 1];
            }
    }
}

// ---------------------------------------------------------------------------
// Fused kernel — EXACT R10 config (best measured: 27.1 us).
// TT=4, 512 CTAs, tt 0,1 MUFU.TANH; tt 2,3 shared-E + bit-seed + 2-Newton rcp.
// ---------------------------------------------------------------------------
__global__ __launch_bounds__(512) void fused_attn(
    const float* __restrict__ w2, const float* __restrict__ b2p,
    const int* __restrict__ mask, float* __restrict__ out)
{
    const int b   = blockIdx.y;
    const int tg  = blockIdx.x;
    const int tid = threadIdx.x;
    const int s   = tid & 127;
    const int hg  = tid >> 7;

    __shared__ float qs[4][H_DIM];        // rows 0,1: q; rows 2,3: Eq = 2^(2q*log2e)
    __shared__ float w2s[H_DIM];
    __shared__ float part[4][4][S_DIM];
    __shared__ float redm[4][4];
    __shared__ float reds[4][4];

    const float LOG2E     = 1.442695040888963407f;
    const float TWO_LOG2E = 2.885390081777926815f;

    for (int idx = tid; idx < 4 * H_DIM; idx += 512) {
        const int tt = idx >> 8;
        const int h  = idx & (H_DIM - 1);
        const int t  = tg * 4 + tt;
        const float q = g_q_proj[((size_t)t * B_DIM + b) * H_DIM + h];
        qs[tt][h] = (tt >= 2) ? ex2f_(q * TWO_LOG2E) : q;
    }
    if (tid < H_DIM) w2s[tid] = w2[tid];
    __syncthreads();

    const float* __restrict__ srcb = g_src_proj + (size_t)b * H_DIM * S_DIM + s;
    const int h0 = hg * 64;

    float a0 = 0.f, a1 = 0.f, a2 = 0.f, a3 = 0.f, wsum = 0.f;
#pragma unroll 4
    for (int i = 0; i < 64; i++) {
        const int h = h0 + i;
        const float sv = srcb[h * S_DIM];
        const float w  = w2s[h];
        wsum += w;
        a0 = fmaf(w, tanhf_(sv + qs[0][h]), a0);
        a1 = fmaf(w, tanhf_(sv + qs[1][h]), a1);
        const float E = ex2f_(sv * TWO_LOG2E);
        {
            const float d = fmaf(E, qs[2][h], 1.f);
            float r = __uint_as_float(0x7EF311C3u - __float_as_uint(d));
            r = r * fmaf(-d, r, 2.f);
            r = r * fmaf(-d, r, 2.f);
            a2 = fmaf(w, r, a2);
        }
        {
            const float d = fmaf(E, qs[3][h], 1.f);
            float r = __uint_as_float(0x7EF311C3u - __float_as_uint(d));
            r = r * fmaf(-d, r, 2.f);
            r = r * fmaf(-d, r, 2.f);
            a3 = fmaf(w, r, a3);
        }
    }
    part[0][hg][s] = a0;
    part[1][hg][s] = a1;
    part[2][hg][s] = fmaf(-2.f, a2, wsum);
    part[3][hg][s] = fmaf(-2.f, a3, wsum);
    __syncthreads();

    float logit = ((part[hg][0][s] + part[hg][1][s]) +
                   (part[hg][2][s] + part[hg][3][s])) + b2p[0];
    if (mask[b * S_DIM + s] != 0)
        logit = __int_as_float(0xff800000);

    const int lane = tid & 31;
    const int gw   = (tid >> 5) & 3;

    float m = logit;
#pragma unroll
    for (int off = 16; off >= 1; off >>= 1)
        m = fmaxf(m, __shfl_xor_sync(0xffffffffu, m, off));
    if (lane == 0) redm[hg][gw] = m;
    __syncthreads();

    const float bm = fmaxf(fmaxf(redm[hg][0], redm[hg][1]),
                           fmaxf(redm[hg][2], redm[hg][3]));
    const float e = ex2f_((logit - bm) * LOG2E);
    float sum = e;
#pragma unroll
    for (int off = 16; off >= 1; off >>= 1)
        sum += __shfl_xor_sync(0xffffffffu, sum, off);
    if (lane == 0) reds[hg][gw] = sum;
    __syncthreads();

    const float tot = (reds[hg][0] + reds[hg][1]) + (reds[hg][2] + reds[hg][3]);
    const int t = tg * 4 + hg;
    out[((size_t)t * B_DIM + b) * S_DIM + s] = e / tot;
}

extern "C" void kernel_launch(void* const* d_in, const int* in_sizes, int n_in,
                              void* d_out, int out_size)
{
    const float* src  = (const float*)d_in[0];
    const int*   mask = (const int*)d_in[1];
    const float* qv   = (const float*)d_in[2];
    const float* Wsrc = (const float*)d_in[3];
    const float* bsrc = (const float*)d_in[4];
    const float* Wq   = (const float*)d_in[5];
    const float* bq   = (const float*)d_in[6];
    const float* w2   = (const float*)d_in[7];
    const float* b2   = (const float*)d_in[8];
    float*       out  = (float*)d_out;

    dim3 g1(48, 4);
    proj_gemm<<<g1, 512>>>(src, Wsrc, bsrc, qv, Wq, bq);

    dim3 g2(T_DIM / 4, B_DIM);
    fused_attn<<<g2, 512>>>(w2, b2, mask, out);
}

// round 14
// speedup vs baseline: 1.3685x; 1.0361x over previous
#include <cuda_runtime.h>
#include <cuda_fp16.h>
#include <cstdint>
#include <math_constants.h>

#define T_DIM 64
#define B_DIM 32
#define S_DIM 128
#define E_DIM 512
#define Q_DIM 512
#define H_DIM 256

#define HSTR 40   // halves per smem row (32 data + 8 pad) -> conflict-free frags

// Scratch (device globals — no allocation allowed)
__device__ float g_src_proj[B_DIM * H_DIM * S_DIM];   // [b][h][s]
__device__ float g_q_proj[T_DIM * B_DIM * H_DIM];     // [t][b][h]

__device__ __forceinline__ float ex2f_(float x) {
    float y; asm("ex2.approx.f32 %0, %1;" : "=f"(y) : "f"(x)); return y;
}
__device__ __forceinline__ unsigned h2tanh_(unsigned x) {
    unsigned y; asm("tanh.approx.f16x2 %0, %1;" : "=r"(y) : "r"(x)); return y;
}
__device__ __forceinline__ void mma_f16(float c[4], const unsigned a[4], const unsigned b[2]) {
    asm volatile(
        "mma.sync.aligned.m16n8k16.row.col.f32.f16.f16.f32 "
        "{%0,%1,%2,%3}, {%4,%5,%6,%7}, {%8,%9}, {%0,%1,%2,%3};"
        : "+f"(c[0]), "+f"(c[1]), "+f"(c[2]), "+f"(c[3])
        : "r"(a[0]), "r"(a[1]), "r"(a[2]), "r"(a[3]), "r"(b[0]), "r"(b[1]));
}

// ---------------------------------------------------------------------------
// FP16 tensor-core projection GEMM (unchanged from R12 — measured win).
// ---------------------------------------------------------------------------
__global__ __launch_bounds__(512) void proj_gemm(
    const float* __restrict__ src, const float* __restrict__ Wsrc, const float* __restrict__ bsrc,
    const float* __restrict__ qv,  const float* __restrict__ Wq,   const float* __restrict__ bq)
{
    __shared__ __align__(16) __half As[2][128][HSTR];
    __shared__ __align__(16) __half Bs[2][64][HSTR];

    const int bx = blockIdx.x;      // 0..47
    const int n0 = blockIdx.y * 64; // h tile base

    const bool is_src = (bx < 32);
    const float* __restrict__ A    = is_src ? (src + (size_t)bx * 128 * E_DIM)
                                            : (qv  + (size_t)(bx - 32) * 128 * Q_DIM);
    const float* __restrict__ W    = is_src ? Wsrc : Wq;
    const float* __restrict__ bias = is_src ? bsrc : bq;

    const int tid  = threadIdx.x;
    const int warp = tid >> 5;
    const int lane = tid & 31;
    const int wm   = (warp & 3) * 32;
    const int wn   = (warp >> 2) * 16;
    const int frow = lane >> 2;
    const int fcol = lane & 3;

    float acc[2][2][4];
#pragma unroll
    for (int i = 0; i < 2; i++)
#pragma unroll
        for (int j = 0; j < 2; j++)
#pragma unroll
            for (int r = 0; r < 4; r++) acc[i][j][r] = 0.f;

    float4 ra0, ra1, rb;
    const int a_r0 = tid >> 3;
    const int a_r1 = (tid + 512) >> 3;
    const int a_c  = (tid & 7) * 4;

    auto ldg_chunk = [&](int kc) {
        const int kt = kc * 32;
        ra0 = *(const float4*)&A[(size_t)a_r0 * 512 + kt + a_c];
        ra1 = *(const float4*)&A[(size_t)a_r1 * 512 + kt + a_c];
        rb  = *(const float4*)&W[(size_t)(n0 + a_r0) * 512 + kt + a_c];
    };
    auto sts_chunk = [&](int buf) {
        *(__half2*)&As[buf][a_r0][a_c    ] = __floats2half2_rn(ra0.x, ra0.y);
        *(__half2*)&As[buf][a_r0][a_c + 2] = __floats2half2_rn(ra0.z, ra0.w);
        *(__half2*)&As[buf][a_r1][a_c    ] = __floats2half2_rn(ra1.x, ra1.y);
        *(__half2*)&As[buf][a_r1][a_c + 2] = __floats2half2_rn(ra1.z, ra1.w);
        *(__half2*)&Bs[buf][a_r0][a_c    ] = __floats2half2_rn(rb.x, rb.y);
        *(__half2*)&Bs[buf][a_r0][a_c + 2] = __floats2half2_rn(rb.z, rb.w);
    };

    ldg_chunk(0);
    sts_chunk(0);

    for (int kc = 0; kc < 16; kc++) {
        __syncthreads();
        if (kc + 1 < 16) ldg_chunk(kc + 1);

        const int buf = kc & 1;
#pragma unroll
        for (int ks = 0; ks < 2; ks++) {
            const int kb = ks * 16 + fcol * 2;
            unsigned ah[2][4];
#pragma unroll
            for (int mf = 0; mf < 2; mf++) {
                const int m = wm + mf * 16 + frow;
                ah[mf][0] = *(const unsigned*)&As[buf][m    ][kb    ];
                ah[mf][1] = *(const unsigned*)&As[buf][m + 8][kb    ];
                ah[mf][2] = *(const unsigned*)&As[buf][m    ][kb + 8];
                ah[mf][3] = *(const unsigned*)&As[buf][m + 8][kb + 8];
            }
            unsigned bh[2][2];
#pragma unroll
            for (int nf = 0; nf < 2; nf++) {
                const int n = wn + nf * 8 + frow;
                bh[nf][0] = *(const unsigned*)&Bs[buf][n][kb    ];
                bh[nf][1] = *(const unsigned*)&Bs[buf][n][kb + 8];
            }
#pragma unroll
            for (int mf = 0; mf < 2; mf++)
#pragma unroll
                for (int nf = 0; nf < 2; nf++)
                    mma_f16(acc[mf][nf], ah[mf], bh[nf]);
        }

        if (kc + 1 < 16) sts_chunk((kc + 1) & 1);
    }

    const int crow = lane >> 2;
    const int ccol = (lane & 3) * 2;

    if (is_src) {
        const int b = bx;
        float* dst = g_src_proj + (size_t)b * H_DIM * S_DIM;
#pragma unroll
        for (int mf = 0; mf < 2; mf++)
#pragma unroll
            for (int nf = 0; nf < 2; nf++) {
                const int s0  = wm + mf * 16 + crow;
                const int h0g = n0 + wn + nf * 8 + ccol;
                dst[(h0g    ) * S_DIM + s0    ] = acc[mf][nf][0] + bias[h0g    ];
                dst[(h0g + 1) * S_DIM + s0    ] = acc[mf][nf][1] + bias[h0g + 1];
                dst[(h0g    ) * S_DIM + s0 + 8] = acc[mf][nf][2] + bias[h0g    ];
                dst[(h0g + 1) * S_DIM + s0 + 8] = acc[mf][nf][3] + bias[h0g + 1];
            }
    } else {
        const int m0 = (bx - 32) * 128;
#pragma unroll
        for (int mf = 0; mf < 2; mf++)
#pragma unroll
            for (int nf = 0; nf < 2; nf++) {
                const int m   = m0 + wm + mf * 16 + crow;
                const int h0g = n0 + wn + nf * 8 + ccol;
                g_q_proj[(size_t)m * H_DIM + h0g    ]       = acc[mf][nf][0] + bias[h0g    ];
                g_q_proj[(size_t)m * H_DIM + h0g + 1]       = acc[mf][nf][1] + bias[h0g + 1];
                g_q_proj[(size_t)(m + 8) * H_DIM + h0g    ] = acc[mf][nf][2] + bias[h0g    ];
                g_q_proj[(size_t)(m + 8) * H_DIM + h0g + 1] = acc[mf][nf][3] + bias[h0g + 1];
            }
    }
}

// ---------------------------------------------------------------------------
// Fused kernel (TT=4, 512 CTAs — proven launch shape) with tanh.approx.f16x2:
//   args x = sv + q computed in f32, packed RNE to half2 (one rounding),
//   2 MUFU.TANH.F16x2 per iter cover all 4 t's (32 MUFU-cyc vs f32's 48).
//   Unpack to f32, accumulate in f32 (no f16 accumulation error).
// ---------------------------------------------------------------------------
__global__ __launch_bounds__(512) void fused_attn(
    const float* __restrict__ w2, const float* __restrict__ b2p,
    const int* __restrict__ mask, float* __restrict__ out)
{
    const int b   = blockIdx.y;
    const int tg  = blockIdx.x;
    const int tid = threadIdx.x;
    const int s   = tid & 127;
    const int hg  = tid >> 7;

    __shared__ float4 qsv[H_DIM];         // q for 4 t's, packed per h
    __shared__ float  w2s[H_DIM];
    __shared__ float  part[4][4][S_DIM];
    __shared__ float  redm[4][4];
    __shared__ float  reds[4][4];

    const float LOG2E = 1.442695040888963407f;

    for (int idx = tid; idx < 4 * H_DIM; idx += 512) {
        const int tt = idx >> 8;
        const int h  = idx & (H_DIM - 1);
        const int t  = tg * 4 + tt;
        ((float*)qsv)[h * 4 + tt] = g_q_proj[((size_t)t * B_DIM + b) * H_DIM + h];
    }
    if (tid < H_DIM) w2s[tid] = w2[tid];
    __syncthreads();

    const float* __restrict__ srcb = g_src_proj + (size_t)b * H_DIM * S_DIM + s;
    const int h0 = hg * 64;

    float a0 = 0.f, a1 = 0.f, a2 = 0.f, a3 = 0.f;
#pragma unroll 4
    for (int i = 0; i < 64; i++) {
        const int h = h0 + i;
        const float sv = srcb[h * S_DIM];
        const float w  = w2s[h];
        const float4 qt = qsv[h];

        const __half2 p01 = __floats2half2_rn(sv + qt.x, sv + qt.y);
        const __half2 p23 = __floats2half2_rn(sv + qt.z, sv + qt.w);
        unsigned t01 = h2tanh_(*(const unsigned*)&p01);
        unsigned t23 = h2tanh_(*(const unsigned*)&p23);
        const float2 f01 = __half22float2(*(const __half2*)&t01);
        const float2 f23 = __half22float2(*(const __half2*)&t23);

        a0 = fmaf(w, f01.x, a0);
        a1 = fmaf(w, f01.y, a1);
        a2 = fmaf(w, f23.x, a2);
        a3 = fmaf(w, f23.y, a3);
    }
    part[0][hg][s] = a0;
    part[1][hg][s] = a1;
    part[2][hg][s] = a2;
    part[3][hg][s] = a3;
    __syncthreads();

    float logit = ((part[hg][0][s] + part[hg][1][s]) +
                   (part[hg][2][s] + part[hg][3][s])) + b2p[0];
    if (mask[b * S_DIM + s] != 0)
        logit = __int_as_float(0xff800000);

    const int lane = tid & 31;
    const int gw   = (tid >> 5) & 3;

    float m = logit;
#pragma unroll
    for (int off = 16; off >= 1; off >>= 1)
        m = fmaxf(m, __shfl_xor_sync(0xffffffffu, m, off));
    if (lane == 0) redm[hg][gw] = m;
    __syncthreads();

    const float bm = fmaxf(fmaxf(redm[hg][0], redm[hg][1]),
                           fmaxf(redm[hg][2], redm[hg][3]));
    const float e = ex2f_((logit - bm) * LOG2E);
    float sum = e;
#pragma unroll
    for (int off = 16; off >= 1; off >>= 1)
        sum += __shfl_xor_sync(0xffffffffu, sum, off);
    if (lane == 0) reds[hg][gw] = sum;
    __syncthreads();

    const float tot = (reds[hg][0] + reds[hg][1]) + (reds[hg][2] + reds[hg][3]);
    const int t = tg * 4 + hg;
    out[((size_t)t * B_DIM + b) * S_DIM + s] = e / tot;
}

extern "C" void kernel_launch(void* const* d_in, const int* in_sizes, int n_in,
                              void* d_out, int out_size)
{
    const float* src  = (const float*)d_in[0];
    const int*   mask = (const int*)d_in[1];
    const float* qv   = (const float*)d_in[2];
    const float* Wsrc = (const float*)d_in[3];
    const float* bsrc = (const float*)d_in[4];
    const float* Wq   = (const float*)d_in[5];
    const float* bq   = (const float*)d_in[6];
    const float* w2   = (const float*)d_in[7];
    const float* b2   = (const float*)d_in[8];
    float*       out  = (float*)d_out;

    dim3 g1(48, 4);
    proj_gemm<<<g1, 512>>>(src, Wsrc, bsrc, qv, Wq, bq);

    dim3 g2(T_DIM / 4, B_DIM);
    fused_attn<<<g2, 512>>>(w2, b2, mask, out);
}

// round 15
// speedup vs baseline: 1.4145x; 1.0336x over previous
#include <cuda_runtime.h>
#include <cuda_fp16.h>
#include <cstdint>
#include <math_constants.h>

#define T_DIM 64
#define B_DIM 32
#define S_DIM 128
#define E_DIM 512
#define Q_DIM 512
#define H_DIM 256

#define HSTR 40   // halves per smem row (32 data + 8 pad) -> conflict-free frags

// Scratch (device globals — no allocation allowed)
__device__ float g_src_proj[B_DIM * H_DIM * S_DIM];   // [b][h][s]
__device__ float g_q_proj[T_DIM * B_DIM * H_DIM];     // [t][b][h]

__device__ __forceinline__ float ex2f_(float x) {
    float y; asm("ex2.approx.f32 %0, %1;" : "=f"(y) : "f"(x)); return y;
}
__device__ __forceinline__ unsigned h2tanh_(unsigned x) {
    unsigned y; asm("tanh.approx.f16x2 %0, %1;" : "=r"(y) : "r"(x)); return y;
}
__device__ __forceinline__ void mma_f16(float c[4], const unsigned a[4], const unsigned b[2]) {
    asm volatile(
        "mma.sync.aligned.m16n8k16.row.col.f32.f16.f16.f32 "
        "{%0,%1,%2,%3}, {%4,%5,%6,%7}, {%8,%9}, {%0,%1,%2,%3};"
        : "+f"(c[0]), "+f"(c[1]), "+f"(c[2]), "+f"(c[3])
        : "r"(a[0]), "r"(a[1]), "r"(a[2]), "r"(a[3]), "r"(b[0]), "r"(b[1]));
}

// ---------------------------------------------------------------------------
// FP16 tensor-core projection GEMM (unchanged — measured win at ~14 us).
// ---------------------------------------------------------------------------
__global__ __launch_bounds__(512) void proj_gemm(
    const float* __restrict__ src, const float* __restrict__ Wsrc, const float* __restrict__ bsrc,
    const float* __restrict__ qv,  const float* __restrict__ Wq,   const float* __restrict__ bq)
{
    __shared__ __align__(16) __half As[2][128][HSTR];
    __shared__ __align__(16) __half Bs[2][64][HSTR];

    const int bx = blockIdx.x;      // 0..47
    const int n0 = blockIdx.y * 64; // h tile base

    const bool is_src = (bx < 32);
    const float* __restrict__ A    = is_src ? (src + (size_t)bx * 128 * E_DIM)
                                            : (qv  + (size_t)(bx - 32) * 128 * Q_DIM);
    const float* __restrict__ W    = is_src ? Wsrc : Wq;
    const float* __restrict__ bias = is_src ? bsrc : bq;

    const int tid  = threadIdx.x;
    const int warp = tid >> 5;
    const int lane = tid & 31;
    const int wm   = (warp & 3) * 32;
    const int wn   = (warp >> 2) * 16;
    const int frow = lane >> 2;
    const int fcol = lane & 3;

    float acc[2][2][4];
#pragma unroll
    for (int i = 0; i < 2; i++)
#pragma unroll
        for (int j = 0; j < 2; j++)
#pragma unroll
            for (int r = 0; r < 4; r++) acc[i][j][r] = 0.f;

    float4 ra0, ra1, rb;
    const int a_r0 = tid >> 3;
    const int a_r1 = (tid + 512) >> 3;
    const int a_c  = (tid & 7) * 4;

    auto ldg_chunk = [&](int kc) {
        const int kt = kc * 32;
        ra0 = *(const float4*)&A[(size_t)a_r0 * 512 + kt + a_c];
        ra1 = *(const float4*)&A[(size_t)a_r1 * 512 + kt + a_c];
        rb  = *(const float4*)&W[(size_t)(n0 + a_r0) * 512 + kt + a_c];
    };
    auto sts_chunk = [&](int buf) {
        *(__half2*)&As[buf][a_r0][a_c    ] = __floats2half2_rn(ra0.x, ra0.y);
        *(__half2*)&As[buf][a_r0][a_c + 2] = __floats2half2_rn(ra0.z, ra0.w);
        *(__half2*)&As[buf][a_r1][a_c    ] = __floats2half2_rn(ra1.x, ra1.y);
        *(__half2*)&As[buf][a_r1][a_c + 2] = __floats2half2_rn(ra1.z, ra1.w);
        *(__half2*)&Bs[buf][a_r0][a_c    ] = __floats2half2_rn(rb.x, rb.y);
        *(__half2*)&Bs[buf][a_r0][a_c + 2] = __floats2half2_rn(rb.z, rb.w);
    };

    ldg_chunk(0);
    sts_chunk(0);

    for (int kc = 0; kc < 16; kc++) {
        __syncthreads();
        if (kc + 1 < 16) ldg_chunk(kc + 1);

        const int buf = kc & 1;
#pragma unroll
        for (int ks = 0; ks < 2; ks++) {
            const int kb = ks * 16 + fcol * 2;
            unsigned ah[2][4];
#pragma unroll
            for (int mf = 0; mf < 2; mf++) {
                const int m = wm + mf * 16 + frow;
                ah[mf][0] = *(const unsigned*)&As[buf][m    ][kb    ];
                ah[mf][1] = *(const unsigned*)&As[buf][m + 8][kb    ];
                ah[mf][2] = *(const unsigned*)&As[buf][m    ][kb + 8];
                ah[mf][3] = *(const unsigned*)&As[buf][m + 8][kb + 8];
            }
            unsigned bh[2][2];
#pragma unroll
            for (int nf = 0; nf < 2; nf++) {
                const int n = wn + nf * 8 + frow;
                bh[nf][0] = *(const unsigned*)&Bs[buf][n][kb    ];
                bh[nf][1] = *(const unsigned*)&Bs[buf][n][kb + 8];
            }
#pragma unroll
            for (int mf = 0; mf < 2; mf++)
#pragma unroll
                for (int nf = 0; nf < 2; nf++)
                    mma_f16(acc[mf][nf], ah[mf], bh[nf]);
        }

        if (kc + 1 < 16) sts_chunk((kc + 1) & 1);
    }

    const int crow = lane >> 2;
    const int ccol = (lane & 3) * 2;

    if (is_src) {
        const int b = bx;
        float* dst = g_src_proj + (size_t)b * H_DIM * S_DIM;
#pragma unroll
        for (int mf = 0; mf < 2; mf++)
#pragma unroll
            for (int nf = 0; nf < 2; nf++) {
                const int s0  = wm + mf * 16 + crow;
                const int h0g = n0 + wn + nf * 8 + ccol;
                dst[(h0g    ) * S_DIM + s0    ] = acc[mf][nf][0] + bias[h0g    ];
                dst[(h0g + 1) * S_DIM + s0    ] = acc[mf][nf][1] + bias[h0g + 1];
                dst[(h0g    ) * S_DIM + s0 + 8] = acc[mf][nf][2] + bias[h0g    ];
                dst[(h0g + 1) * S_DIM + s0 + 8] = acc[mf][nf][3] + bias[h0g + 1];
            }
    } else {
        const int m0 = (bx - 32) * 128;
#pragma unroll
        for (int mf = 0; mf < 2; mf++)
#pragma unroll
            for (int nf = 0; nf < 2; nf++) {
                const int m   = m0 + wm + mf * 16 + crow;
                const int h0g = n0 + wn + nf * 8 + ccol;
                g_q_proj[(size_t)m * H_DIM + h0g    ]       = acc[mf][nf][0] + bias[h0g    ];
                g_q_proj[(size_t)m * H_DIM + h0g + 1]       = acc[mf][nf][1] + bias[h0g + 1];
                g_q_proj[(size_t)(m + 8) * H_DIM + h0g    ] = acc[mf][nf][2] + bias[h0g    ];
                g_q_proj[(size_t)(m + 8) * H_DIM + h0g + 1] = acc[mf][nf][3] + bias[h0g + 1];
            }
    }
}

// ---------------------------------------------------------------------------
// Fused kernel v2 — all-f16 inner loop, converts amortized.
// 512 thr: sp = tid&63 (s-pair, s = 2sp,2sp+1 in f16x2 lanes), hgr = tid>>6
// (8 H-slices of 32 h). Per iter: 1 LDG.64 + 1 F2FP pack + 4x(HADD2,TANH2,HFMA2).
// half2 accumulators promoted to f32 every 8 iters (cvt amortized to ~1/iter).
// ---------------------------------------------------------------------------
__global__ __launch_bounds__(512) void fused_attn(
    const float* __restrict__ w2, const float* __restrict__ b2p,
    const int* __restrict__ mask, float* __restrict__ out)
{
    const int b   = blockIdx.y;
    const int tg  = blockIdx.x;            // t = tg*4 + tt
    const int tid = threadIdx.x;

    __shared__ unsigned w2h[H_DIM];        // half2(w,w)
    __shared__ uint4    qpk[H_DIM];        // {half2(q0,q0),...,half2(q3,q3)}
    __shared__ float    part[4][8][S_DIM]; // 16 KB
    __shared__ float    redm[4][4];
    __shared__ float    reds[4][4];

    const float LOG2E = 1.442695040888963407f;

    for (int idx = tid; idx < 4 * H_DIM; idx += 512) {
        const int tt = idx >> 8;
        const int h  = idx & (H_DIM - 1);
        const int t  = tg * 4 + tt;
        const __half hq = __float2half_rn(g_q_proj[((size_t)t * B_DIM + b) * H_DIM + h]);
        const __half2 d = __half2half2(hq);
        ((unsigned*)&qpk[h])[tt] = *(const unsigned*)&d;
    }
    if (tid < H_DIM) {
        const __half hw = __float2half_rn(w2[tid]);
        const __half2 d = __half2half2(hw);
        w2h[tid] = *(const unsigned*)&d;
    }
    __syncthreads();

    const int sp  = tid & 63;
    const int hgr = tid >> 6;              // 0..7
    const int s0  = sp * 2;
    const int h0  = hgr * 32;

    const float* __restrict__ srcp = g_src_proj + (size_t)b * H_DIM * S_DIM + s0;

    float facc[4][2];
#pragma unroll
    for (int t = 0; t < 4; t++) { facc[t][0] = 0.f; facc[t][1] = 0.f; }

#pragma unroll
    for (int c = 0; c < 4; c++) {
        __half2 hacc0 = __floats2half2_rn(0.f, 0.f);
        __half2 hacc1 = hacc0, hacc2 = hacc0, hacc3 = hacc0;

#pragma unroll
        for (int i = 0; i < 8; i++) {
            const int h = h0 + c * 8 + i;
            const float2 svf = *(const float2*)&srcp[(size_t)h * S_DIM];
            const __half2 sv2 = __floats2half2_rn(svf.x, svf.y);
            const uint4 qp = qpk[h];
            const unsigned wv = w2h[h];
            const __half2 wh = *(const __half2*)&wv;

            __half2 a0 = __hadd2(sv2, *(const __half2*)&qp.x);
            __half2 a1 = __hadd2(sv2, *(const __half2*)&qp.y);
            __half2 a2 = __hadd2(sv2, *(const __half2*)&qp.z);
            __half2 a3 = __hadd2(sv2, *(const __half2*)&qp.w);
            unsigned t0 = h2tanh_(*(const unsigned*)&a0);
            unsigned t1 = h2tanh_(*(const unsigned*)&a1);
            unsigned t2 = h2tanh_(*(const unsigned*)&a2);
            unsigned t3 = h2tanh_(*(const unsigned*)&a3);
            hacc0 = __hfma2(wh, *(const __half2*)&t0, hacc0);
            hacc1 = __hfma2(wh, *(const __half2*)&t1, hacc1);
            hacc2 = __hfma2(wh, *(const __half2*)&t2, hacc2);
            hacc3 = __hfma2(wh, *(const __half2*)&t3, hacc3);
        }
        {
            const float2 f0 = __half22float2(hacc0);
            const float2 f1 = __half22float2(hacc1);
            const float2 f2 = __half22float2(hacc2);
            const float2 f3 = __half22float2(hacc3);
            facc[0][0] += f0.x; facc[0][1] += f0.y;
            facc[1][0] += f1.x; facc[1][1] += f1.y;
            facc[2][0] += f2.x; facc[2][1] += f2.y;
            facc[3][0] += f3.x; facc[3][1] += f3.y;
        }
    }

#pragma unroll
    for (int t = 0; t < 4; t++)
        *(float2*)&part[t][hgr][s0] = make_float2(facc[t][0], facc[t][1]);
    __syncthreads();

    const int s    = tid & 127;
    const int ttg  = tid >> 7;
    const int lane = tid & 31;
    const int gw   = (tid >> 5) & 3;

    float logit = b2p[0];
#pragma unroll
    for (int g = 0; g < 8; g++)
        logit += part[ttg][g][s];
    if (mask[b * S_DIM + s] != 0)
        logit = __int_as_float(0xff800000);

    float m = logit;
#pragma unroll
    for (int off = 16; off >= 1; off >>= 1)
        m = fmaxf(m, __shfl_xor_sync(0xffffffffu, m, off));
    if (lane == 0) redm[ttg][gw] = m;
    __syncthreads();

    const float bm = fmaxf(fmaxf(redm[ttg][0], redm[ttg][1]),
                           fmaxf(redm[ttg][2], redm[ttg][3]));
    const float e = ex2f_((logit - bm) * LOG2E);
    float sum = e;
#pragma unroll
    for (int off = 16; off >= 1; off >>= 1)
        sum += __shfl_xor_sync(0xffffffffu, sum, off);
    if (lane == 0) reds[ttg][gw] = sum;
    __syncthreads();

    const float tot = (reds[ttg][0] + reds[ttg][1]) + (reds[ttg][2] + reds[ttg][3]);
    const int t = tg * 4 + ttg;
    out[((size_t)t * B_DIM + b) * S_DIM + s] = e / tot;
}

extern "C" void kernel_launch(void* const* d_in, const int* in_sizes, int n_in,
                              void* d_out, int out_size)
{
    const float* src  = (const float*)d_in[0];
    const int*   mask = (const int*)d_in[1];
    const float* qv   = (const float*)d_in[2];
    const float* Wsrc = (const float*)d_in[3];
    const float* bsrc = (const float*)d_in[4];
    const float* Wq   = (const float*)d_in[5];
    const float* bq   = (const float*)d_in[6];
    const float* w2   = (const float*)d_in[7];
    const float* b2   = (const float*)d_in[8];
    float*       out  = (float*)d_out;

    dim3 g1(48, 4);
    proj_gemm<<<g1, 512>>>(src, Wsrc, bsrc, qv, Wq, bq);

    dim3 g2(T_DIM / 4, B_DIM);
    fused_attn<<<g2, 512>>>(w2, b2, mask, out);
}

// round 16
// speedup vs baseline: 1.4376x; 1.0163x over previous
#include <cuda_runtime.h>
#include <cuda_fp16.h>
#include <cstdint>
#include <math_constants.h>

#define T_DIM 64
#define B_DIM 32
#define S_DIM 128
#define E_DIM 512
#define Q_DIM 512
#define H_DIM 256

#define HSTR 40   // halves per smem row (32 data + 8 pad) -> conflict-free frags

// Scratch (device globals — no allocation allowed)
__device__ __half g_src_proj_h[B_DIM * H_DIM * S_DIM];  // [b][h][s], f16 (same rounding point as before)
__device__ float  g_q_proj[T_DIM * B_DIM * H_DIM];      // [t][b][h]

__device__ __forceinline__ float ex2f_(float x) {
    float y; asm("ex2.approx.f32 %0, %1;" : "=f"(y) : "f"(x)); return y;
}
__device__ __forceinline__ unsigned h2tanh_(unsigned x) {
    unsigned y; asm("tanh.approx.f16x2 %0, %1;" : "=r"(y) : "r"(x)); return y;
}
__device__ __forceinline__ void mma_f16(float c[4], const unsigned a[4], const unsigned b[2]) {
    asm volatile(
        "mma.sync.aligned.m16n8k16.row.col.f32.f16.f16.f32 "
        "{%0,%1,%2,%3}, {%4,%5,%6,%7}, {%8,%9}, {%0,%1,%2,%3};"
        : "+f"(c[0]), "+f"(c[1]), "+f"(c[2]), "+f"(c[3])
        : "r"(a[0]), "r"(a[1]), "r"(a[2]), "r"(a[3]), "r"(b[0]), "r"(b[1]));
}

// ---------------------------------------------------------------------------
// FP16 tensor-core projection GEMM. Mainloop unchanged (measured ~14 us).
// src-path epilogue now emits __half (RNE after f32 bias add — numerically
// identical to the old f32-store + in-loop pack).
// ---------------------------------------------------------------------------
__global__ __launch_bounds__(512) void proj_gemm(
    const float* __restrict__ src, const float* __restrict__ Wsrc, const float* __restrict__ bsrc,
    const float* __restrict__ qv,  const float* __restrict__ Wq,   const float* __restrict__ bq)
{
    __shared__ __align__(16) __half As[2][128][HSTR];
    __shared__ __align__(16) __half Bs[2][64][HSTR];

    const int bx = blockIdx.x;      // 0..47
    const int n0 = blockIdx.y * 64; // h tile base

    const bool is_src = (bx < 32);
    const float* __restrict__ A    = is_src ? (src + (size_t)bx * 128 * E_DIM)
                                            : (qv  + (size_t)(bx - 32) * 128 * Q_DIM);
    const float* __restrict__ W    = is_src ? Wsrc : Wq;
    const float* __restrict__ bias = is_src ? bsrc : bq;

    const int tid  = threadIdx.x;
    const int warp = tid >> 5;
    const int lane = tid & 31;
    const int wm   = (warp & 3) * 32;
    const int wn   = (warp >> 2) * 16;
    const int frow = lane >> 2;
    const int fcol = lane & 3;

    float acc[2][2][4];
#pragma unroll
    for (int i = 0; i < 2; i++)
#pragma unroll
        for (int j = 0; j < 2; j++)
#pragma unroll
            for (int r = 0; r < 4; r++) acc[i][j][r] = 0.f;

    float4 ra0, ra1, rb;
    const int a_r0 = tid >> 3;
    const int a_r1 = (tid + 512) >> 3;
    const int a_c  = (tid & 7) * 4;

    auto ldg_chunk = [&](int kc) {
        const int kt = kc * 32;
        ra0 = *(const float4*)&A[(size_t)a_r0 * 512 + kt + a_c];
        ra1 = *(const float4*)&A[(size_t)a_r1 * 512 + kt + a_c];
        rb  = *(const float4*)&W[(size_t)(n0 + a_r0) * 512 + kt + a_c];
    };
    auto sts_chunk = [&](int buf) {
        *(__half2*)&As[buf][a_r0][a_c    ] = __floats2half2_rn(ra0.x, ra0.y);
        *(__half2*)&As[buf][a_r0][a_c + 2] = __floats2half2_rn(ra0.z, ra0.w);
        *(__half2*)&As[buf][a_r1][a_c    ] = __floats2half2_rn(ra1.x, ra1.y);
        *(__half2*)&As[buf][a_r1][a_c + 2] = __floats2half2_rn(ra1.z, ra1.w);
        *(__half2*)&Bs[buf][a_r0][a_c    ] = __floats2half2_rn(rb.x, rb.y);
        *(__half2*)&Bs[buf][a_r0][a_c + 2] = __floats2half2_rn(rb.z, rb.w);
    };

    ldg_chunk(0);
    sts_chunk(0);

    for (int kc = 0; kc < 16; kc++) {
        __syncthreads();
        if (kc + 1 < 16) ldg_chunk(kc + 1);

        const int buf = kc & 1;
#pragma unroll
        for (int ks = 0; ks < 2; ks++) {
            const int kb = ks * 16 + fcol * 2;
            unsigned ah[2][4];
#pragma unroll
            for (int mf = 0; mf < 2; mf++) {
                const int m = wm + mf * 16 + frow;
                ah[mf][0] = *(const unsigned*)&As[buf][m    ][kb    ];
                ah[mf][1] = *(const unsigned*)&As[buf][m + 8][kb    ];
                ah[mf][2] = *(const unsigned*)&As[buf][m    ][kb + 8];
                ah[mf][3] = *(const unsigned*)&As[buf][m + 8][kb + 8];
            }
            unsigned bh[2][2];
#pragma unroll
            for (int nf = 0; nf < 2; nf++) {
                const int n = wn + nf * 8 + frow;
                bh[nf][0] = *(const unsigned*)&Bs[buf][n][kb    ];
                bh[nf][1] = *(const unsigned*)&Bs[buf][n][kb + 8];
            }
#pragma unroll
            for (int mf = 0; mf < 2; mf++)
#pragma unroll
                for (int nf = 0; nf < 2; nf++)
                    mma_f16(acc[mf][nf], ah[mf], bh[nf]);
        }

        if (kc + 1 < 16) sts_chunk((kc + 1) & 1);
    }

    const int crow = lane >> 2;
    const int ccol = (lane & 3) * 2;

    if (is_src) {
        const int b = bx;
        __half* dst = g_src_proj_h + (size_t)b * H_DIM * S_DIM;
#pragma unroll
        for (int mf = 0; mf < 2; mf++)
#pragma unroll
            for (int nf = 0; nf < 2; nf++) {
                const int s0  = wm + mf * 16 + crow;
                const int h0g = n0 + wn + nf * 8 + ccol;
                dst[(h0g    ) * S_DIM + s0    ] = __float2half_rn(acc[mf][nf][0] + bias[h0g    ]);
                dst[(h0g + 1) * S_DIM + s0    ] = __float2half_rn(acc[mf][nf][1] + bias[h0g + 1]);
                dst[(h0g    ) * S_DIM + s0 + 8] = __float2half_rn(acc[mf][nf][2] + bias[h0g    ]);
                dst[(h0g + 1) * S_DIM + s0 + 8] = __float2half_rn(acc[mf][nf][3] + bias[h0g + 1]);
            }
    } else {
        const int m0 = (bx - 32) * 128;
#pragma unroll
        for (int mf = 0; mf < 2; mf++)
#pragma unroll
            for (int nf = 0; nf < 2; nf++) {
                const int m   = m0 + wm + mf * 16 + crow;
                const int h0g = n0 + wn + nf * 8 + ccol;
                g_q_proj[(size_t)m * H_DIM + h0g    ]       = acc[mf][nf][0] + bias[h0g    ];
                g_q_proj[(size_t)m * H_DIM + h0g + 1]       = acc[mf][nf][1] + bias[h0g + 1];
                g_q_proj[(size_t)(m + 8) * H_DIM + h0g    ] = acc[mf][nf][2] + bias[h0g    ];
                g_q_proj[(size_t)(m + 8) * H_DIM + h0g + 1] = acc[mf][nf][3] + bias[h0g + 1];
            }
    }
}

// ---------------------------------------------------------------------------
// Fused kernel v3 — all-f16 inner loop, src_proj pre-rounded to f16 in gmem:
// per iter now 1 LDG.32 (half2) + 4x(HADD2, TANH2, HFMA2). No per-iter pack.
// ---------------------------------------------------------------------------
__global__ __launch_bounds__(512) void fused_attn(
    const float* __restrict__ w2, const float* __restrict__ b2p,
    const int* __restrict__ mask, float* __restrict__ out)
{
    const int b   = blockIdx.y;
    const int tg  = blockIdx.x;            // t = tg*4 + tt
    const int tid = threadIdx.x;

    __shared__ unsigned w2h[H_DIM];        // half2(w,w)
    __shared__ uint4    qpk[H_DIM];        // {half2(q0,q0),...,half2(q3,q3)}
    __shared__ float    part[4][8][S_DIM]; // 16 KB
    __shared__ float    redm[4][4];
    __shared__ float    reds[4][4];

    const float LOG2E = 1.442695040888963407f;

    for (int idx = tid; idx < 4 * H_DIM; idx += 512) {
        const int tt = idx >> 8;
        const int h  = idx & (H_DIM - 1);
        const int t  = tg * 4 + tt;
        const __half hq = __float2half_rn(g_q_proj[((size_t)t * B_DIM + b) * H_DIM + h]);
        const __half2 d = __half2half2(hq);
        ((unsigned*)&qpk[h])[tt] = *(const unsigned*)&d;
    }
    if (tid < H_DIM) {
        const __half hw = __float2half_rn(w2[tid]);
        const __half2 d = __half2half2(hw);
        w2h[tid] = *(const unsigned*)&d;
    }
    __syncthreads();

    const int sp  = tid & 63;
    const int hgr = tid >> 6;              // 0..7
    const int s0  = sp * 2;
    const int h0  = hgr * 32;

    const __half* __restrict__ srcp = g_src_proj_h + (size_t)b * H_DIM * S_DIM + s0;

    float facc[4][2];
#pragma unroll
    for (int t = 0; t < 4; t++) { facc[t][0] = 0.f; facc[t][1] = 0.f; }

#pragma unroll
    for (int c = 0; c < 4; c++) {
        __half2 hacc0 = __floats2half2_rn(0.f, 0.f);
        __half2 hacc1 = hacc0, hacc2 = hacc0, hacc3 = hacc0;

#pragma unroll
        for (int i = 0; i < 8; i++) {
            const int h = h0 + c * 8 + i;
            const __half2 sv2 = *(const __half2*)&srcp[(size_t)h * S_DIM];
            const uint4 qp = qpk[h];
            const unsigned wv = w2h[h];
            const __half2 wh = *(const __half2*)&wv;

            __half2 a0 = __hadd2(sv2, *(const __half2*)&qp.x);
            __half2 a1 = __hadd2(sv2, *(const __half2*)&qp.y);
            __half2 a2 = __hadd2(sv2, *(const __half2*)&qp.z);
            __half2 a3 = __hadd2(sv2, *(const __half2*)&qp.w);
            unsigned t0 = h2tanh_(*(const unsigned*)&a0);
            unsigned t1 = h2tanh_(*(const unsigned*)&a1);
            unsigned t2 = h2tanh_(*(const unsigned*)&a2);
            unsigned t3 = h2tanh_(*(const unsigned*)&a3);
            hacc0 = __hfma2(wh, *(const __half2*)&t0, hacc0);
            hacc1 = __hfma2(wh, *(const __half2*)&t1, hacc1);
            hacc2 = __hfma2(wh, *(const __half2*)&t2, hacc2);
            hacc3 = __hfma2(wh, *(const __half2*)&t3, hacc3);
        }
        {
            const float2 f0 = __half22float2(hacc0);
            const float2 f1 = __half22float2(hacc1);
            const float2 f2 = __half22float2(hacc2);
            const float2 f3 = __half22float2(hacc3);
            facc[0][0] += f0.x; facc[0][1] += f0.y;
            facc[1][0] += f1.x; facc[1][1] += f1.y;
            facc[2][0] += f2.x; facc[2][1] += f2.y;
            facc[3][0] += f3.x; facc[3][1] += f3.y;
        }
    }

#pragma unroll
    for (int t = 0; t < 4; t++)
        *(float2*)&part[t][hgr][s0] = make_float2(facc[t][0], facc[t][1]);
    __syncthreads();

    const int s    = tid & 127;
    const int ttg  = tid >> 7;
    const int lane = tid & 31;
    const int gw   = (tid >> 5) & 3;

    float logit = b2p[0];
#pragma unroll
    for (int g = 0; g < 8; g++)
        logit += part[ttg][g][s];
    if (mask[b * S_DIM + s] != 0)
        logit = __int_as_float(0xff800000);

    float m = logit;
#pragma unroll
    for (int off = 16; off >= 1; off >>= 1)
        m = fmaxf(m, __shfl_xor_sync(0xffffffffu, m, off));
    if (lane == 0) redm[ttg][gw] = m;
    __syncthreads();

    const float bm = fmaxf(fmaxf(redm[ttg][0], redm[ttg][1]),
                           fmaxf(redm[ttg][2], redm[ttg][3]));
    const float e = ex2f_((logit - bm) * LOG2E);
    float sum = e;
#pragma unroll
    for (int off = 16; off >= 1; off >>= 1)
        sum += __shfl_xor_sync(0xffffffffu, sum, off);
    if (lane == 0) reds[ttg][gw] = sum;
    __syncthreads();

    const float tot = (reds[ttg][0] + reds[ttg][1]) + (reds[ttg][2] + reds[ttg][3]);
    const int t = tg * 4 + ttg;
    out[((size_t)t * B_DIM + b) * S_DIM + s] = e / tot;
}

extern "C" void kernel_launch(void* const* d_in, const int* in_sizes, int n_in,
                              void* d_out, int out_size)
{
    const float* src  = (const float*)d_in[0];
    const int*   mask = (const int*)d_in[1];
    const float* qv   = (const float*)d_in[2];
    const float* Wsrc = (const float*)d_in[3];
    const float* bsrc = (const float*)d_in[4];
    const float* Wq   = (const float*)d_in[5];
    const float* bq   = (const float*)d_in[6];
    const float* w2   = (const float*)d_in[7];
    const float* b2   = (const float*)d_in[8];
    float*       out  = (float*)d_out;

    dim3 g1(48, 4);
    proj_gemm<<<g1, 512>>>(src, Wsrc, bsrc, qv, Wq, bq);

    dim3 g2(T_DIM / 4, B_DIM);
    fused_attn<<<g2, 512>>>(w2, b2, mask, out);
}